// round 1
// baseline (speedup 1.0000x reference)
#include <cuda_runtime.h>

#define NROWS 4096
#define TWO_N 8192
#define DDIM  64
#define BM 128
#define BN 128
#define CS 4
#define TILES 16            // (TWO_N / BN) / CS
#define INV_T 20.0f         // 1 / 0.05

// Scratch (allocation-free rule: __device__ globals), re-zeroed every launch.
__device__ float g_total[TWO_N];
__device__ float g_same[TWO_N];
__device__ int   g_cnt[64];

__global__ void prep_zero() {
    int i = blockIdx.x * blockDim.x + threadIdx.x;
    if (i < TWO_N) { g_total[i] = 0.f; g_same[i] = 0.f; }
}

__global__ void prep_hist(const int* __restrict__ label, float* __restrict__ out) {
    __shared__ int h[64];
    int t = threadIdx.x;
    if (t < 64) h[t] = 0;
    __syncthreads();
    for (int i = t; i < NROWS; i += blockDim.x) atomicAdd(&h[label[i] & 63], 1);
    __syncthreads();
    if (t < 64) g_cnt[t] = h[t];
    if (t == 0) out[0] = 0.f;
}

// Fused GEMM + exp + label-masked row-sum.
// Grid: (TWO_N/BM, CS). Block: 256 threads = 16x16, each owns an 8x8 micro-tile
// (rows ty*4..+3 and 64+ty*4..+3; cols tx*4..+3 and 64+tx*4..+3).
// SMEM tiles are k-major float4 with XOR swizzle for conflict-free LDS.128.
__global__ __launch_bounds__(256, 2) void sim_kernel(
    const float* __restrict__ f1, const float* __restrict__ f2,
    const int* __restrict__ label) {
    extern __shared__ char smem[];
    float4* As4 = (float4*)smem;            // [64][32] float4
    float4* Bs4 = As4 + 64 * 32;            // [64][32] float4
    int*    labB = (int*)(Bs4 + 64 * 32);   // [BN]
    float*  redt = (float*)(labB + BN);     // [BM]
    float*  reds = redt + BM;               // [BM]

    const int tid = threadIdx.x;
    const int tx = tid & 15, ty = tid >> 4;
    const int row0 = blockIdx.x * BM;

    // Load A tile: global [r][k] row-major -> SMEM k-major swizzled.
    {
        float* Asf = (float*)As4;
        for (int t = tid; t < BM * (DDIM / 4); t += 256) {
            int r = t >> 4, k4 = t & 15;
            int gr = row0 + r;
            const float* src = (gr < NROWS) ? (f1 + gr * DDIM) : (f2 + (gr - NROWS) * DDIM);
            float4 v = ((const float4*)src)[k4];
            int k = k4 * 4;
            int c4 = r >> 2, lo = r & 3;
            Asf[(k + 0) * BM + (((c4 ^ ((k + 0) & 31)) << 2) | lo)] = v.x;
            Asf[(k + 1) * BM + (((c4 ^ ((k + 1) & 31)) << 2) | lo)] = v.y;
            Asf[(k + 2) * BM + (((c4 ^ ((k + 2) & 31)) << 2) | lo)] = v.z;
            Asf[(k + 3) * BM + (((c4 ^ ((k + 3) & 31)) << 2) | lo)] = v.w;
        }
    }

    int labR[8];
#pragma unroll
    for (int i = 0; i < 8; i++) {
        int lr = ((i >> 2) << 6) + ty * 4 + (i & 3);
        labR[i] = label[(row0 + lr) & (NROWS - 1)];
    }

    float tot[8] = {0, 0, 0, 0, 0, 0, 0, 0};
    float sm [8] = {0, 0, 0, 0, 0, 0, 0, 0};

    for (int tile = 0; tile < TILES; tile++) {
        int col0 = (blockIdx.y * TILES + tile) * BN;
        __syncthreads();   // protect Bs/labB from previous iteration (and order As first iter)
        {
            float* Bsf = (float*)Bs4;
            for (int t = tid; t < BN * (DDIM / 4); t += 256) {
                int r = t >> 4, k4 = t & 15;
                int gc = col0 + r;
                const float* src = (gc < NROWS) ? (f1 + gc * DDIM) : (f2 + (gc - NROWS) * DDIM);
                float4 v = ((const float4*)src)[k4];
                int k = k4 * 4;
                int c4 = r >> 2, lo = r & 3;
                Bsf[(k + 0) * BN + (((c4 ^ ((k + 0) & 31)) << 2) | lo)] = v.x;
                Bsf[(k + 1) * BN + (((c4 ^ ((k + 1) & 31)) << 2) | lo)] = v.y;
                Bsf[(k + 2) * BN + (((c4 ^ ((k + 2) & 31)) << 2) | lo)] = v.z;
                Bsf[(k + 3) * BN + (((c4 ^ ((k + 3) & 31)) << 2) | lo)] = v.w;
            }
            if (tid < BN) labB[tid] = label[(col0 + tid) & (NROWS - 1)];
        }
        __syncthreads();

        float acc[8][8];
#pragma unroll
        for (int i = 0; i < 8; i++)
#pragma unroll
            for (int j = 0; j < 8; j++) acc[i][j] = 0.f;

#pragma unroll 8
        for (int k = 0; k < DDIM; k++) {
            int s = k & 31;
            float4 a0 = As4[k * 32 + (ty ^ s)];
            float4 a1 = As4[k * 32 + ((16 + ty) ^ s)];
            float4 b0 = Bs4[k * 32 + (tx ^ s)];
            float4 b1 = Bs4[k * 32 + ((16 + tx) ^ s)];
            float a[8] = {a0.x, a0.y, a0.z, a0.w, a1.x, a1.y, a1.z, a1.w};
            float b[8] = {b0.x, b0.y, b0.z, b0.w, b1.x, b1.y, b1.z, b1.w};
#pragma unroll
            for (int i = 0; i < 8; i++)
#pragma unroll
                for (int j = 0; j < 8; j++) acc[i][j] = fmaf(a[i], b[j], acc[i][j]);
        }

        // Fused epilogue: exp + masked row accumulation (diagonal falls in `sm`).
#pragma unroll
        for (int j = 0; j < 8; j++) {
            int lc = ((j >> 2) << 6) + tx * 4 + (j & 3);
            int lb = labB[lc];
#pragma unroll
            for (int i = 0; i < 8; i++) {
                float e = __expf(acc[i][j] * INV_T);
                tot[i] += e;
                sm[i]  += (labR[i] == lb) ? e : 0.f;
            }
        }
    }

    // Block-level row reduction, then one global atomic per row per block.
    if (tid < BM) { redt[tid] = 0.f; reds[tid] = 0.f; }
    __syncthreads();
#pragma unroll
    for (int i = 0; i < 8; i++) {
        int lr = ((i >> 2) << 6) + ty * 4 + (i & 3);
        atomicAdd(&redt[lr], tot[i]);
        atomicAdd(&reds[lr], sm[i]);
    }
    __syncthreads();
    if (tid < BM) {
        atomicAdd(&g_total[row0 + tid], redt[tid]);
        atomicAdd(&g_same [row0 + tid], reds[tid]);
    }
}

__global__ void finalize_kernel(const float* __restrict__ f1, const float* __restrict__ f2,
                                const int* __restrict__ label, float* __restrict__ out) {
    int i = blockIdx.x * blockDim.x + threadIdx.x;
    float val = 0.f;
    if (i < TWO_N) {
        int i0 = i & (NROWS - 1);
        const float4* a = (const float4*)(f1 + i0 * DDIM);
        const float4* b = (const float4*)(f2 + i0 * DDIM);
        float d = 0.f;
#pragma unroll
        for (int u = 0; u < DDIM / 4; u++) {
            float4 x = a[u], y = b[u];
            d += x.x * y.x + x.y * y.y + x.z * y.z + x.w * y.w;
        }
        float pos  = __expf(d * INV_T);
        float Ng   = g_total[i] - g_same[i];
        float term = log1pf(Ng / pos);           // == -log(pos/(Ng+pos))
        int   gs   = 2 * g_cnt[label[i0] & 63];  // group_size
        val = term / (float)gs;
    }
#pragma unroll
    for (int o = 16; o > 0; o >>= 1) val += __shfl_down_sync(0xffffffffu, val, o);
    __shared__ float ws[8];
    int lane = threadIdx.x & 31, w = threadIdx.x >> 5;
    if (lane == 0) ws[w] = val;
    __syncthreads();
    if (w == 0) {
        val = (lane < 8) ? ws[lane] : 0.f;
#pragma unroll
        for (int o = 4; o > 0; o >>= 1) val += __shfl_down_sync(0xffffffffu, val, o);
        if (lane == 0) atomicAdd(out, val);
    }
}

extern "C" void kernel_launch(void* const* d_in, const int* in_sizes, int n_in,
                              void* d_out, int out_size) {
    (void)in_sizes; (void)n_in; (void)out_size;
    const float* f1    = (const float*)d_in[0];
    const float* f2    = (const float*)d_in[1];
    const int*   label = (const int*)d_in[2];
    float*       out   = (float*)d_out;

    const int smem_bytes = 64 * 32 * 16 * 2 + BN * (int)sizeof(int) + 2 * BM * (int)sizeof(float);
    cudaFuncSetAttribute(sim_kernel, cudaFuncAttributeMaxDynamicSharedMemorySize, smem_bytes);

    prep_zero<<<(TWO_N + 255) / 256, 256>>>();
    prep_hist<<<1, 256>>>(label, out);
    dim3 grid(TWO_N / BM, CS);
    sim_kernel<<<grid, 256, smem_bytes>>>(f1, f2, label);
    finalize_kernel<<<TWO_N / 256, 256>>>(f1, f2, label, out);
}

// round 3
// speedup vs baseline: 4.3904x; 4.3904x over previous
#include <cuda_runtime.h>
#include <cstdint>

#define NROWS 4096
#define TWO_N 8192
#define DDIM  64
#define BM 128
#define BN 128
#define CS 4
#define NT 16
#define NSLICE 8
#define INV_T 20.0f
#define LOG2E_T 28.853900817779268f   // 20 * log2(e)

// dynamic smem layout
#define OFF_A     0        // 128x64 bf16, swizzled 128B rows (16KB)
#define OFF_B     16384    // 128x64 bf16, swizzled (16KB)
#define OFF_STAGE 32768    // 128x64 fp32 cp.async staging (32KB)
#define OFF_LAB   65536    // int labels, 2 buffers x 128 (1KB)
#define SMEM_BYTES 66560

__device__ float g_pt[NSLICE][TWO_N];
__device__ float g_ps[NSLICE][TWO_N];
__device__ int   g_cnt[64];

static __device__ __forceinline__ uint32_t smem_u32(const void* p) {
    uint32_t a;
    asm("{ .reg .u64 t; cvta.to.shared.u64 t, %1; cvt.u32.u64 %0, t; }" : "=r"(a) : "l"(p));
    return a;
}
static __device__ __forceinline__ float ex2f(float x) {
    float r; asm("ex2.approx.f32 %0, %1;" : "=f"(r) : "f"(x)); return r;
}
static __device__ __forceinline__ uint32_t bf16pack(float lo, float hi) {
    uint32_t r; asm("cvt.rn.bf16x2.f32 %0, %1, %2;" : "=r"(r) : "f"(hi), "f"(lo)); return r;
}
static __device__ __forceinline__ void cpa16(uint32_t dst, const void* src) {
    asm volatile("cp.async.ca.shared.global [%0], [%1], 16;" :: "r"(dst), "l"(src));
}

#define LDSM4(r0, r1, r2, r3, addr) \
    asm volatile("ldmatrix.sync.aligned.m8n8.x4.shared.b16 {%0,%1,%2,%3}, [%4];" \
                 : "=r"(r0), "=r"(r1), "=r"(r2), "=r"(r3) : "r"(addr))

#define MMA16816(d, a, b0, b1) \
    asm volatile("mma.sync.aligned.m16n8k16.row.col.f32.bf16.bf16.f32 " \
                 "{%0,%1,%2,%3}, {%4,%5,%6,%7}, {%8,%9}, {%0,%1,%2,%3};" \
                 : "+f"((d)[0]), "+f"((d)[1]), "+f"((d)[2]), "+f"((d)[3]) \
                 : "r"((a)[0]), "r"((a)[1]), "r"((a)[2]), "r"((a)[3]), "r"(b0), "r"(b1))

__global__ void __launch_bounds__(256, 2)
sim_kernel(const float* __restrict__ f1, const float* __restrict__ f2,
           const int* __restrict__ label) {
    extern __shared__ __align__(1024) char smem[];
    const uint32_t sb = smem_u32(smem);
    const int tid  = threadIdx.x;
    const int lane = tid & 31;
    const int wid  = tid >> 5;
    const int warpM = wid >> 1;       // 0..3
    const int warpN = wid & 1;        // 0..1
    const int row0 = blockIdx.x * BM;
    const int csb  = blockIdx.y;
    int* labBuf = (int*)(smem + OFF_LAB);

    // ---- prologue: stage B tile 0 via cp.async, convert A tile, labels ----
    {
        int col0 = csb * NT * BN;
#pragma unroll
        for (int it = 0; it < 8; it++) {
            int s = it * 256 + tid;          // float4 slot
            int r = s >> 4, q = s & 15;
            int gc = col0 + r;
            const float* src = (gc < NROWS) ? (f1 + gc * DDIM) : (f2 + (gc - NROWS) * DDIM);
            cpa16(sb + OFF_STAGE + s * 16, src + q * 4);
        }
        asm volatile("cp.async.commit_group;" ::: "memory");
        if (tid < 128) labBuf[tid] = label[(col0 + tid) & (NROWS - 1)];
    }
#pragma unroll
    for (int it = 0; it < 8; it++) {
        int s = it * 256 + tid;
        int r = s >> 4, q = s & 15;
        int gr = row0 + r;
        const float4* src = (gr < NROWS) ? (const float4*)(f1 + gr * DDIM)
                                         : (const float4*)(f2 + (gr - NROWS) * DDIM);
        float4 v = src[q];
        uint2 p = make_uint2(bf16pack(v.x, v.y), bf16pack(v.z, v.w));
        *(uint2*)(smem + OFF_A + r * 128 + ((q * 8) ^ ((r & 7) << 4))) = p;
    }

    // per-thread row labels + fragment address components
    int labR[4];
    int rowA[2], nB[4];
#pragma unroll
    for (int mb = 0; mb < 2; mb++) {
        rowA[mb] = warpM * 32 + mb * 16 + (lane & 7) + ((lane >> 3) & 1) * 8;
#pragma unroll
        for (int h = 0; h < 2; h++) {
            int grow = row0 + warpM * 32 + mb * 16 + (lane >> 2) + h * 8;
            labR[mb * 2 + h] = label[grow & (NROWS - 1)];
        }
    }
#pragma unroll
    for (int pr = 0; pr < 4; pr++)
        nB[pr] = warpN * 64 + pr * 16 + (lane & 7) + ((lane >> 4) & 1) * 8;
    const int kaA = (lane >> 4) * 16;          // A k-byte offset within chunk
    const int kbB = ((lane >> 3) & 1) * 16;    // B k-byte offset within chunk

    float tot[4] = {0.f, 0.f, 0.f, 0.f};
    float smv[4] = {0.f, 0.f, 0.f, 0.f};

    asm volatile("cp.async.wait_group 0;" ::: "memory");
    __syncthreads();

    for (int t = 0; t < NT; t++) {
        // convert staged fp32 -> swizzled bf16 B tile
#pragma unroll
        for (int it = 0; it < 8; it++) {
            int s = it * 256 + tid;
            int r = s >> 4, q = s & 15;
            float4 v = *(const float4*)(smem + OFF_STAGE + s * 16);
            uint2 p = make_uint2(bf16pack(v.x, v.y), bf16pack(v.z, v.w));
            *(uint2*)(smem + OFF_B + r * 128 + ((q * 8) ^ ((r & 7) << 4))) = p;
        }
        __syncthreads();

        // prefetch next tile into stage (overlaps MMA below)
        if (t + 1 < NT) {
            int col0n = (csb * NT + t + 1) * BN;
#pragma unroll
            for (int it = 0; it < 8; it++) {
                int s = it * 256 + tid;
                int r = s >> 4, q = s & 15;
                int gc = col0n + r;
                const float* src = (gc < NROWS) ? (f1 + gc * DDIM) : (f2 + (gc - NROWS) * DDIM);
                cpa16(sb + OFF_STAGE + s * 16, src + q * 4);
            }
            asm volatile("cp.async.commit_group;" ::: "memory");
            if (tid < 128) labBuf[((t + 1) & 1) * 128 + tid] = label[(col0n + tid) & (NROWS - 1)];
        }

        // ---- MMA: warp tile 32x64 over k=64 ----
        float acc[2][8][4];
#pragma unroll
        for (int mb = 0; mb < 2; mb++)
#pragma unroll
            for (int nb = 0; nb < 8; nb++)
#pragma unroll
                for (int e = 0; e < 4; e++) acc[mb][nb][e] = 0.f;

#pragma unroll
        for (int kc = 0; kc < 4; kc++) {
            uint32_t a[2][4];
#pragma unroll
            for (int mb = 0; mb < 2; mb++) {
                uint32_t addr = sb + OFF_A + rowA[mb] * 128
                              + ((kc * 32 + kaA) ^ ((rowA[mb] & 7) << 4));
                LDSM4(a[mb][0], a[mb][1], a[mb][2], a[mb][3], addr);
            }
#pragma unroll
            for (int pr = 0; pr < 4; pr++) {
                uint32_t b0, b1, b2, b3;
                uint32_t addr = sb + OFF_B + nB[pr] * 128
                              + ((kc * 32 + kbB) ^ ((nB[pr] & 7) << 4));
                LDSM4(b0, b1, b2, b3, addr);
#pragma unroll
                for (int mb = 0; mb < 2; mb++) {
                    MMA16816(acc[mb][2 * pr],     a[mb], b0, b1);
                    MMA16816(acc[mb][2 * pr + 1], a[mb], b2, b3);
                }
            }
        }

        // ---- fused epilogue: exp + label-masked row accumulation ----
        const int* lb = labBuf + (t & 1) * 128 + warpN * 64;
#pragma unroll
        for (int nb = 0; nb < 8; nb++) {
            int2 lb2 = *(const int2*)(lb + nb * 8 + (lane & 3) * 2);
#pragma unroll
            for (int mb = 0; mb < 2; mb++)
#pragma unroll
                for (int h = 0; h < 2; h++) {
                    float e0 = ex2f(acc[mb][nb][2 * h]     * LOG2E_T);
                    float e1 = ex2f(acc[mb][nb][2 * h + 1] * LOG2E_T);
                    tot[mb * 2 + h] += e0 + e1;
                    float s0 = (lb2.x == labR[mb * 2 + h]) ? e0 : 0.f;
                    float s1 = (lb2.y == labR[mb * 2 + h]) ? e1 : 0.f;
                    smv[mb * 2 + h] += s0 + s1;
                }
        }

        asm volatile("cp.async.wait_group 0;" ::: "memory");
        __syncthreads();
    }

    // quad reduction (lanes sharing a row differ only in lane&3) + plain store
#pragma unroll
    for (int i = 0; i < 4; i++) {
        float tv = tot[i], sv = smv[i];
        tv += __shfl_xor_sync(0xffffffffu, tv, 1);
        tv += __shfl_xor_sync(0xffffffffu, tv, 2);
        sv += __shfl_xor_sync(0xffffffffu, sv, 1);
        sv += __shfl_xor_sync(0xffffffffu, sv, 2);
        if ((lane & 3) == 0) {
            int grow = row0 + warpM * 32 + (i >> 1) * 16 + (lane >> 2) + (i & 1) * 8;
            g_pt[csb * 2 + warpN][grow] = tv;
            g_ps[csb * 2 + warpN][grow] = sv;
        }
    }
}

__global__ void prep_hist(const int* __restrict__ label, float* __restrict__ out) {
    __shared__ int h[64];
    int t = threadIdx.x;
    if (t < 64) h[t] = 0;
    __syncthreads();
    for (int i = t; i < NROWS; i += blockDim.x) atomicAdd(&h[label[i] & 63], 1);
    __syncthreads();
    if (t < 64) g_cnt[t] = h[t];
    if (t == 0) out[0] = 0.f;
}

__global__ void finalize_kernel(const float* __restrict__ f1, const float* __restrict__ f2,
                                const int* __restrict__ label, float* __restrict__ out) {
    int i = blockIdx.x * blockDim.x + threadIdx.x;
    float val = 0.f;
    if (i < TWO_N) {
        int i0 = i & (NROWS - 1);
        const float4* a = (const float4*)(f1 + i0 * DDIM);
        const float4* b = (const float4*)(f2 + i0 * DDIM);
        float d = 0.f;
#pragma unroll
        for (int u = 0; u < DDIM / 4; u++) {
            float4 x = a[u], y = b[u];
            d += x.x * y.x + x.y * y.y + x.z * y.z + x.w * y.w;
        }
        float tot = 0.f, sm = 0.f;
#pragma unroll
        for (int s = 0; s < NSLICE; s++) { tot += g_pt[s][i]; sm += g_ps[s][i]; }
        float pos  = __expf(d * INV_T);
        float Ng   = tot - sm;
        float term = log1pf(Ng / pos);            // == -log(pos/(Ng+pos))
        int   gs   = 2 * g_cnt[label[i0] & 63];
        val = term / (float)gs;
    }
#pragma unroll
    for (int o = 16; o > 0; o >>= 1) val += __shfl_down_sync(0xffffffffu, val, o);
    __shared__ float ws[8];
    int lane = threadIdx.x & 31, w = threadIdx.x >> 5;
    if (lane == 0) ws[w] = val;
    __syncthreads();
    if (w == 0) {
        val = (lane < 8) ? ws[lane] : 0.f;
#pragma unroll
        for (int o = 4; o > 0; o >>= 1) val += __shfl_down_sync(0xffffffffu, val, o);
        if (lane == 0) atomicAdd(out, val);
    }
}

extern "C" void kernel_launch(void* const* d_in, const int* in_sizes, int n_in,
                              void* d_out, int out_size) {
    (void)in_sizes; (void)n_in; (void)out_size;
    const float* f1    = (const float*)d_in[0];
    const float* f2    = (const float*)d_in[1];
    const int*   label = (const int*)d_in[2];
    float*       out   = (float*)d_out;

    cudaFuncSetAttribute(sim_kernel, cudaFuncAttributeMaxDynamicSharedMemorySize, SMEM_BYTES);

    prep_hist<<<1, 256>>>(label, out);
    dim3 grid(TWO_N / BM, CS);
    sim_kernel<<<grid, 256, SMEM_BYTES>>>(f1, f2, label);
    finalize_kernel<<<TWO_N / 256, 256>>>(f1, f2, label, out);
}

// round 4
// speedup vs baseline: 5.2308x; 1.1914x over previous
#include <cuda_runtime.h>
#include <cstdint>

#define NROWS 4096
#define TWO_N 8192
#define DDIM  64
#define BM 128
#define BN 128
#define CS 4
#define NT 16
#define NSLICE 8
#define INV_T 20.0f
#define PRESCALE 5.3715827f        // sqrt(20 * log2(e)); dot of scaled = exponent for ex2

// dynamic smem layout (sim kernel)
#define OFF_A   0                  // 128x64 bf16 swizzled (16KB)
#define OFF_B   16384              // 3 stages x 16KB
#define OFF_LAB 65536              // 2048 labels for this column split (8KB)
#define SMEM_BYTES 73728

// pre-scaled bf16 features, concat(f1,f2), row-major 128B rows
__device__ __align__(128) uint2 g_feat[TWO_N * 16];   // 16 x uint2 (8B) per row
__device__ float g_pt[NSLICE][TWO_N];
__device__ float g_ps[NSLICE][TWO_N];
__device__ int   g_cnt[64];

static __device__ __forceinline__ uint32_t smem_u32(const void* p) {
    uint32_t a;
    asm("{ .reg .u64 t; cvta.to.shared.u64 t, %1; cvt.u32.u64 %0, t; }" : "=r"(a) : "l"(p));
    return a;
}
static __device__ __forceinline__ float ex2f(float x) {
    float r; asm("ex2.approx.f32 %0, %1;" : "=f"(r) : "f"(x)); return r;
}
static __device__ __forceinline__ uint32_t bf16pack(float lo, float hi) {
    uint32_t r; asm("cvt.rn.bf16x2.f32 %0, %1, %2;" : "=r"(r) : "f"(hi), "f"(lo)); return r;
}
static __device__ __forceinline__ void cpa16(uint32_t dst, const void* src) {
    asm volatile("cp.async.ca.shared.global [%0], [%1], 16;" :: "r"(dst), "l"(src));
}
#define CP_COMMIT() asm volatile("cp.async.commit_group;" ::: "memory")
#define CP_WAIT(n)  asm volatile("cp.async.wait_group %0;" :: "n"(n) : "memory")

#define LDSM4(r0, r1, r2, r3, addr) \
    asm volatile("ldmatrix.sync.aligned.m8n8.x4.shared.b16 {%0,%1,%2,%3}, [%4];" \
                 : "=r"(r0), "=r"(r1), "=r"(r2), "=r"(r3) : "r"(addr))

#define MMA16816(d, a, b0, b1) \
    asm volatile("mma.sync.aligned.m16n8k16.row.col.f32.bf16.bf16.f32 " \
                 "{%0,%1,%2,%3}, {%4,%5,%6,%7}, {%8,%9}, {%0,%1,%2,%3};" \
                 : "+f"((d)[0]), "+f"((d)[1]), "+f"((d)[2]), "+f"((d)[3]) \
                 : "r"((a)[0]), "r"((a)[1]), "r"((a)[2]), "r"((a)[3]), "r"(b0), "r"(b1))

// ---- prep: fp32 -> prescaled bf16 (blocks 0..63) + hist/zero (block 64) ----
__global__ void __launch_bounds__(256)
prep_kernel(const float* __restrict__ f1, const float* __restrict__ f2,
            const int* __restrict__ label, float* __restrict__ out) {
    const int tid = threadIdx.x;
    if (blockIdx.x < 64) {
        int base = blockIdx.x * 128;
#pragma unroll
        for (int it = 0; it < 8; it++) {
            int s = it * 256 + tid;          // float4 slot within 128x64 chunk
            int r = s >> 4, q = s & 15;
            int gr = base + r;
            const float4* src = (gr < NROWS) ? (const float4*)(f1 + gr * DDIM)
                                             : (const float4*)(f2 + (gr - NROWS) * DDIM);
            float4 v = src[q];
            g_feat[gr * 16 + q] = make_uint2(bf16pack(v.x * PRESCALE, v.y * PRESCALE),
                                             bf16pack(v.z * PRESCALE, v.w * PRESCALE));
        }
    } else {
        __shared__ int h[64];
        if (tid < 64) h[tid] = 0;
        __syncthreads();
        for (int i = tid; i < NROWS; i += 256) atomicAdd(&h[label[i] & 63], 1);
        __syncthreads();
        if (tid < 64) g_cnt[tid] = h[tid];
        if (tid == 0) out[0] = 0.f;
    }
}

// ---- sim: bf16 mma.sync GEMM + fused exp + masked row sums ----
static __device__ __forceinline__ void issue_btile(uint32_t sb, int buf, int col0, int tid) {
    const char* gb = (const char*)g_feat;
#pragma unroll
    for (int it = 0; it < 4; it++) {
        int s = it * 256 + tid;              // 1024 chunks of 16B
        int r = s >> 3, c = s & 7;
        uint32_t dst = sb + OFF_B + buf * 16384 + r * 128 + ((c * 16) ^ ((r & 7) << 4));
        cpa16(dst, gb + (size_t)(col0 + r) * 128 + c * 16);
    }
}

__global__ void __launch_bounds__(256, 2)
sim_kernel(const int* __restrict__ label) {
    extern __shared__ __align__(1024) char smem[];
    const uint32_t sb = smem_u32(smem);
    const int tid  = threadIdx.x;
    const int lane = tid & 31;
    const int wid  = tid >> 5;
    const int warpM = wid >> 1;
    const int warpN = wid & 1;
    const int row0 = blockIdx.x * BM;
    const int csb  = blockIdx.y;
    const int col_base = csb * (NT * BN);    // 2048-aligned

    // ---- prologue: A tile + labels + B0 (group 0), B1 (group 1) ----
    {
        const char* gb = (const char*)g_feat;
#pragma unroll
        for (int it = 0; it < 4; it++) {
            int s = it * 256 + tid;
            int r = s >> 3, c = s & 7;
            uint32_t dst = sb + OFF_A + r * 128 + ((c * 16) ^ ((r & 7) << 4));
            cpa16(dst, gb + (size_t)(row0 + r) * 128 + c * 16);
        }
        const int* lsrc = label + (csb & 1) * 2048;   // (col_base + i) & 4095
#pragma unroll
        for (int it = 0; it < 2; it++) {
            int s = it * 256 + tid;                   // 512 chunks of 16B
            cpa16(sb + OFF_LAB + s * 16, lsrc + s * 4);
        }
        issue_btile(sb, 0, col_base, tid);
        CP_COMMIT();
        issue_btile(sb, 1, col_base + BN, tid);
        CP_COMMIT();
    }

    // per-thread row labels + fragment address components
    int labR[4];
    int rowA[2], nB[4];
#pragma unroll
    for (int mb = 0; mb < 2; mb++) {
        rowA[mb] = warpM * 32 + mb * 16 + (lane & 7) + ((lane >> 3) & 1) * 8;
#pragma unroll
        for (int h = 0; h < 2; h++) {
            int grow = row0 + warpM * 32 + mb * 16 + (lane >> 2) + h * 8;
            labR[mb * 2 + h] = label[grow & (NROWS - 1)];
        }
    }
#pragma unroll
    for (int pr = 0; pr < 4; pr++)
        nB[pr] = warpN * 64 + pr * 16 + (lane & 7) + ((lane >> 4) & 1) * 8;
    const int kaA = (lane >> 4) * 16;
    const int kbB = ((lane >> 3) & 1) * 16;

    float tot[4] = {0.f, 0.f, 0.f, 0.f};
    float smv[4] = {0.f, 0.f, 0.f, 0.f};

    for (int t = 0; t < NT; t++) {
        if (t + 2 < NT) {
            issue_btile(sb, (t + 2) % 3, col_base + (t + 2) * BN, tid);
            CP_COMMIT();
        }
        if (t + 2 < NT)      CP_WAIT(2);
        else if (t + 1 < NT) CP_WAIT(1);
        else                 CP_WAIT(0);
        __syncthreads();

        const uint32_t bBase = sb + OFF_B + (t % 3) * 16384;

        float acc[2][8][4];
#pragma unroll
        for (int mb = 0; mb < 2; mb++)
#pragma unroll
            for (int nb = 0; nb < 8; nb++)
#pragma unroll
                for (int e = 0; e < 4; e++) acc[mb][nb][e] = 0.f;

#pragma unroll
        for (int kc = 0; kc < 4; kc++) {
            uint32_t a[2][4];
#pragma unroll
            for (int mb = 0; mb < 2; mb++) {
                uint32_t addr = sb + OFF_A + rowA[mb] * 128
                              + ((kc * 32 + kaA) ^ ((rowA[mb] & 7) << 4));
                LDSM4(a[mb][0], a[mb][1], a[mb][2], a[mb][3], addr);
            }
#pragma unroll
            for (int pr = 0; pr < 4; pr++) {
                uint32_t b0, b1, b2, b3;
                uint32_t addr = bBase + nB[pr] * 128
                              + ((kc * 32 + kbB) ^ ((nB[pr] & 7) << 4));
                LDSM4(b0, b1, b2, b3, addr);
#pragma unroll
                for (int mb = 0; mb < 2; mb++) {
                    MMA16816(acc[mb][2 * pr],     a[mb], b0, b1);
                    MMA16816(acc[mb][2 * pr + 1], a[mb], b2, b3);
                }
            }
        }

        // fused epilogue: exp (exponent already scaled) + label-masked row sums
        const char* lb = smem + OFF_LAB + (t * 128 + warpN * 64) * 4;
#pragma unroll
        for (int nb = 0; nb < 8; nb++) {
            int2 lb2 = *(const int2*)(lb + (nb * 8 + (lane & 3) * 2) * 4);
#pragma unroll
            for (int mb = 0; mb < 2; mb++)
#pragma unroll
                for (int h = 0; h < 2; h++) {
                    float e0 = ex2f(acc[mb][nb][2 * h]);
                    float e1 = ex2f(acc[mb][nb][2 * h + 1]);
                    tot[mb * 2 + h] += e0 + e1;
                    float s0 = (lb2.x == labR[mb * 2 + h]) ? e0 : 0.f;
                    float s1 = (lb2.y == labR[mb * 2 + h]) ? e1 : 0.f;
                    smv[mb * 2 + h] += s0 + s1;
                }
        }
        __syncthreads();
    }

    // quad reduction + plain per-slice store
#pragma unroll
    for (int i = 0; i < 4; i++) {
        float tv = tot[i], sv = smv[i];
        tv += __shfl_xor_sync(0xffffffffu, tv, 1);
        tv += __shfl_xor_sync(0xffffffffu, tv, 2);
        sv += __shfl_xor_sync(0xffffffffu, sv, 1);
        sv += __shfl_xor_sync(0xffffffffu, sv, 2);
        if ((lane & 3) == 0) {
            int grow = row0 + warpM * 32 + (i >> 1) * 16 + (lane >> 2) + (i & 1) * 8;
            g_pt[csb * 2 + warpN][grow] = tv;
            g_ps[csb * 2 + warpN][grow] = sv;
        }
    }
}

__global__ void finalize_kernel(const float* __restrict__ f1, const float* __restrict__ f2,
                                const int* __restrict__ label, float* __restrict__ out) {
    int i = blockIdx.x * blockDim.x + threadIdx.x;
    float val = 0.f;
    if (i < TWO_N) {
        int i0 = i & (NROWS - 1);
        const float4* a = (const float4*)(f1 + i0 * DDIM);
        const float4* b = (const float4*)(f2 + i0 * DDIM);
        float d = 0.f;
#pragma unroll
        for (int u = 0; u < DDIM / 4; u++) {
            float4 x = a[u], y = b[u];
            d += x.x * y.x + x.y * y.y + x.z * y.z + x.w * y.w;
        }
        float tot = 0.f, sm = 0.f;
#pragma unroll
        for (int s = 0; s < NSLICE; s++) { tot += g_pt[s][i]; sm += g_ps[s][i]; }
        float pos  = __expf(d * INV_T);
        float Ng   = tot - sm;
        float term = log1pf(Ng / pos);            // == -log(pos/(Ng+pos))
        int   gs   = 2 * g_cnt[label[i0] & 63];
        val = term / (float)gs;
    }
#pragma unroll
    for (int o = 16; o > 0; o >>= 1) val += __shfl_down_sync(0xffffffffu, val, o);
    __shared__ float ws[8];
    int lane = threadIdx.x & 31, w = threadIdx.x >> 5;
    if (lane == 0) ws[w] = val;
    __syncthreads();
    if (w == 0) {
        val = (lane < 8) ? ws[lane] : 0.f;
#pragma unroll
        for (int o = 4; o > 0; o >>= 1) val += __shfl_down_sync(0xffffffffu, val, o);
        if (lane == 0) atomicAdd(out, val);
    }
}

extern "C" void kernel_launch(void* const* d_in, const int* in_sizes, int n_in,
                              void* d_out, int out_size) {
    (void)in_sizes; (void)n_in; (void)out_size;
    const float* f1    = (const float*)d_in[0];
    const float* f2    = (const float*)d_in[1];
    const int*   label = (const int*)d_in[2];
    float*       out   = (float*)d_out;

    cudaFuncSetAttribute(sim_kernel, cudaFuncAttributeMaxDynamicSharedMemorySize, SMEM_BYTES);

    prep_kernel<<<65, 256>>>(f1, f2, label, out);
    dim3 grid(TWO_N / BM, CS);
    sim_kernel<<<grid, 256, SMEM_BYTES>>>(label);
    finalize_kernel<<<TWO_N / 256, 256>>>(f1, f2, label, out);
}

// round 5
// speedup vs baseline: 5.6521x; 1.0805x over previous
#include <cuda_runtime.h>
#include <cstdint>

#define NROWS 4096
#define TWO_N 8192
#define DDIM  64
#define BM 128
#define BN 128
#define CS 4
#define NT 16
#define NSLICE 8
#define INV_T 20.0f
#define PRESCALE 5.3715827f        // sqrt(20 * log2(e)); dot of scaled = exponent for ex2

// dynamic smem layout (sim kernel)
#define OFF_A   0                  // 128x64 bf16 swizzled (16KB)
#define OFF_B   16384              // 4 stages x 16KB ring
#define OFF_LAB 81920              // 2048 labels for this column split (8KB)
#define SMEM_BYTES 90112

// pre-scaled bf16 features, concat(f1,f2), row-major 128B rows
__device__ __align__(128) uint2 g_feat[TWO_N * 16];
__device__ float g_pt[NSLICE][TWO_N];
__device__ float g_ps[NSLICE][TWO_N];
__device__ float g_pos[NROWS];
__device__ int   g_cnt[64];

static __device__ __forceinline__ uint32_t smem_u32(const void* p) {
    uint32_t a;
    asm("{ .reg .u64 t; cvta.to.shared.u64 t, %1; cvt.u32.u64 %0, t; }" : "=r"(a) : "l"(p));
    return a;
}
static __device__ __forceinline__ float ex2f(float x) {
    float r; asm("ex2.approx.f32 %0, %1;" : "=f"(r) : "f"(x)); return r;
}
static __device__ __forceinline__ uint32_t bf16pack(float lo, float hi) {
    uint32_t r; asm("cvt.rn.bf16x2.f32 %0, %1, %2;" : "=r"(r) : "f"(hi), "f"(lo)); return r;
}
static __device__ __forceinline__ void cpa16(uint32_t dst, const void* src) {
    asm volatile("cp.async.ca.shared.global [%0], [%1], 16;" :: "r"(dst), "l"(src));
}
#define CP_COMMIT() asm volatile("cp.async.commit_group;" ::: "memory")
#define CP_WAIT(n)  asm volatile("cp.async.wait_group %0;" :: "n"(n) : "memory")

#define LDSM4(r0, r1, r2, r3, addr) \
    asm volatile("ldmatrix.sync.aligned.m8n8.x4.shared.b16 {%0,%1,%2,%3}, [%4];" \
                 : "=r"(r0), "=r"(r1), "=r"(r2), "=r"(r3) : "r"(addr))

#define MMA16816(d, a, b0, b1) \
    asm volatile("mma.sync.aligned.m16n8k16.row.col.f32.bf16.bf16.f32 " \
                 "{%0,%1,%2,%3}, {%4,%5,%6,%7}, {%8,%9}, {%0,%1,%2,%3};" \
                 : "+f"((d)[0]), "+f"((d)[1]), "+f"((d)[2]), "+f"((d)[3]) \
                 : "r"((a)[0]), "r"((a)[1]), "r"((a)[2]), "r"((a)[3]), "r"(b0), "r"(b1))

// ---- prep: convert (blocks 0..127), hist+zero (128), pos dots (129..160) ----
__global__ void __launch_bounds__(256)
prep_kernel(const float* __restrict__ f1, const float* __restrict__ f2,
            const int* __restrict__ label, float* __restrict__ out) {
    const int tid = threadIdx.x;
    const int b = blockIdx.x;
    if (b < 128) {
        int base = b * 64;
#pragma unroll
        for (int it = 0; it < 4; it++) {
            int s = it * 256 + tid;          // float4 slot within 64x64 chunk
            int r = s >> 4, q = s & 15;
            int gr = base + r;
            const float4* src = (gr < NROWS) ? (const float4*)(f1 + gr * DDIM)
                                             : (const float4*)(f2 + (gr - NROWS) * DDIM);
            float4 v = src[q];
            g_feat[gr * 16 + q] = make_uint2(bf16pack(v.x * PRESCALE, v.y * PRESCALE),
                                             bf16pack(v.z * PRESCALE, v.w * PRESCALE));
        }
    } else if (b == 128) {
        __shared__ int h[64];
        if (tid < 64) h[tid] = 0;
        __syncthreads();
        for (int i = tid; i < NROWS; i += 256) atomicAdd(&h[label[i] & 63], 1);
        __syncthreads();
        if (tid < 64) g_cnt[tid] = h[tid];
        if (tid == 0) out[0] = 0.f;
    } else {
        // pos: 32 blocks x 128 rows, two threads per row (halves of the dot)
        int row  = (b - 129) * 128 + (tid >> 1);
        int half = tid & 1;
        const float4* a = (const float4*)(f1 + row * DDIM + half * 32);
        const float4* c = (const float4*)(f2 + row * DDIM + half * 32);
        float d = 0.f;
#pragma unroll
        for (int u = 0; u < 8; u++) {
            float4 x = a[u], y = c[u];
            d += x.x * y.x + x.y * y.y + x.z * y.z + x.w * y.w;
        }
        d += __shfl_xor_sync(0xffffffffu, d, 1);
        if (half == 0) g_pos[row] = __expf(d * INV_T);
    }
}

// ---- sim: bf16 mma.sync GEMM + fused exp + masked row sums ----
static __device__ __forceinline__ void issue_btile(uint32_t sb, int buf, int col0, int tid) {
    const char* gb = (const char*)g_feat;
#pragma unroll
    for (int it = 0; it < 4; it++) {
        int s = it * 256 + tid;              // 1024 chunks of 16B
        int r = s >> 3, c = s & 7;
        uint32_t dst = sb + OFF_B + buf * 16384 + r * 128 + ((c * 16) ^ ((r & 7) << 4));
        cpa16(dst, gb + (size_t)(col0 + r) * 128 + c * 16);
    }
}

__global__ void __launch_bounds__(256, 2)
sim_kernel(const int* __restrict__ label) {
    extern __shared__ __align__(1024) char smem[];
    const uint32_t sb = smem_u32(smem);
    const int tid  = threadIdx.x;
    const int lane = tid & 31;
    const int wid  = tid >> 5;
    const int warpM = wid >> 1;
    const int warpN = wid & 1;
    const int row0 = blockIdx.x * BM;
    const int csb  = blockIdx.y;
    const int col_base = csb * (NT * BN);

    // ---- prologue: A tile + labels + B0 (group 0), B1 (group 1) ----
    {
        const char* gb = (const char*)g_feat;
#pragma unroll
        for (int it = 0; it < 4; it++) {
            int s = it * 256 + tid;
            int r = s >> 3, c = s & 7;
            uint32_t dst = sb + OFF_A + r * 128 + ((c * 16) ^ ((r & 7) << 4));
            cpa16(dst, gb + (size_t)(row0 + r) * 128 + c * 16);
        }
        const int* lsrc = label + (csb & 1) * 2048;   // (col_base + i) & 4095
#pragma unroll
        for (int it = 0; it < 2; it++) {
            int s = it * 256 + tid;
            cpa16(sb + OFF_LAB + s * 16, lsrc + s * 4);
        }
        issue_btile(sb, 0, col_base, tid);
        CP_COMMIT();
        issue_btile(sb, 1, col_base + BN, tid);
        CP_COMMIT();
    }

    int labR[4];
    int rowA[2], nB[4];
#pragma unroll
    for (int mb = 0; mb < 2; mb++) {
        rowA[mb] = warpM * 32 + mb * 16 + (lane & 7) + ((lane >> 3) & 1) * 8;
#pragma unroll
        for (int h = 0; h < 2; h++) {
            int grow = row0 + warpM * 32 + mb * 16 + (lane >> 2) + h * 8;
            labR[mb * 2 + h] = label[grow & (NROWS - 1)];
        }
    }
#pragma unroll
    for (int pr = 0; pr < 4; pr++)
        nB[pr] = warpN * 64 + pr * 16 + (lane & 7) + ((lane >> 4) & 1) * 8;
    const int kaA = (lane >> 4) * 16;
    const int kbB = ((lane >> 3) & 1) * 16;

    float tot[4] = {0.f, 0.f, 0.f, 0.f};
    float smv[4] = {0.f, 0.f, 0.f, 0.f};

    for (int t = 0; t < NT; t++) {
        if (t + 2 < NT) {
            issue_btile(sb, (t + 2) & 3, col_base + (t + 2) * BN, tid);
            CP_COMMIT();
        }
        if (t + 2 < NT)      CP_WAIT(2);
        else if (t + 1 < NT) CP_WAIT(1);
        else                 CP_WAIT(0);
        __syncthreads();      // single barrier per tile (4-deep ring makes reuse safe)

        const uint32_t bBase = sb + OFF_B + (t & 3) * 16384;

        float acc[2][8][4];
#pragma unroll
        for (int mb = 0; mb < 2; mb++)
#pragma unroll
            for (int nb = 0; nb < 8; nb++)
#pragma unroll
                for (int e = 0; e < 4; e++) acc[mb][nb][e] = 0.f;

#pragma unroll
        for (int kc = 0; kc < 4; kc++) {
            uint32_t a[2][4];
#pragma unroll
            for (int mb = 0; mb < 2; mb++) {
                uint32_t addr = sb + OFF_A + rowA[mb] * 128
                              + ((kc * 32 + kaA) ^ ((rowA[mb] & 7) << 4));
                LDSM4(a[mb][0], a[mb][1], a[mb][2], a[mb][3], addr);
            }
#pragma unroll
            for (int pr = 0; pr < 4; pr++) {
                uint32_t b0, b1, b2, b3;
                uint32_t addr = bBase + nB[pr] * 128
                              + ((kc * 32 + kbB) ^ ((nB[pr] & 7) << 4));
                LDSM4(b0, b1, b2, b3, addr);
#pragma unroll
                for (int mb = 0; mb < 2; mb++) {
                    MMA16816(acc[mb][2 * pr],     a[mb], b0, b1);
                    MMA16816(acc[mb][2 * pr + 1], a[mb], b2, b3);
                }
            }
        }

        // fused epilogue: exp (exponent pre-scaled) + label-masked row sums
        const char* lb = smem + OFF_LAB + (t * 128 + warpN * 64) * 4;
#pragma unroll
        for (int nb = 0; nb < 8; nb++) {
            int2 lb2 = *(const int2*)(lb + (nb * 8 + (lane & 3) * 2) * 4);
#pragma unroll
            for (int mb = 0; mb < 2; mb++)
#pragma unroll
                for (int h = 0; h < 2; h++) {
                    float e0 = ex2f(acc[mb][nb][2 * h]);
                    float e1 = ex2f(acc[mb][nb][2 * h + 1]);
                    tot[mb * 2 + h] += e0 + e1;
                    float s0 = (lb2.x == labR[mb * 2 + h]) ? e0 : 0.f;
                    float s1 = (lb2.y == labR[mb * 2 + h]) ? e1 : 0.f;
                    smv[mb * 2 + h] += s0 + s1;
                }
        }
    }

    // quad reduction + plain per-slice store
#pragma unroll
    for (int i = 0; i < 4; i++) {
        float tv = tot[i], sv = smv[i];
        tv += __shfl_xor_sync(0xffffffffu, tv, 1);
        tv += __shfl_xor_sync(0xffffffffu, tv, 2);
        sv += __shfl_xor_sync(0xffffffffu, sv, 1);
        sv += __shfl_xor_sync(0xffffffffu, sv, 2);
        if ((lane & 3) == 0) {
            int grow = row0 + warpM * 32 + (i >> 1) * 16 + (lane >> 2) + (i & 1) * 8;
            g_pt[csb * 2 + warpN][grow] = tv;
            g_ps[csb * 2 + warpN][grow] = sv;
        }
    }
}

__global__ void __launch_bounds__(128)
finalize_kernel(const int* __restrict__ label, float* __restrict__ out) {
    int i = blockIdx.x * blockDim.x + threadIdx.x;   // 64 x 128 = 8192
    int i0 = i & (NROWS - 1);
    float tot = 0.f, sm = 0.f;
#pragma unroll
    for (int s = 0; s < NSLICE; s++) { tot += g_pt[s][i]; sm += g_ps[s][i]; }
    float pos  = g_pos[i0];
    float Ng   = tot - sm;
    float term = log1pf(Ng / pos);            // == -log(pos/(Ng+pos))
    int   gs   = 2 * g_cnt[label[i0] & 63];
    float val  = term / (float)gs;
#pragma unroll
    for (int o = 16; o > 0; o >>= 1) val += __shfl_down_sync(0xffffffffu, val, o);
    __shared__ float ws[4];
    int lane = threadIdx.x & 31, w = threadIdx.x >> 5;
    if (lane == 0) ws[w] = val;
    __syncthreads();
    if (w == 0) {
        val = (lane < 4) ? ws[lane] : 0.f;
#pragma unroll
        for (int o = 2; o > 0; o >>= 1) val += __shfl_down_sync(0xffffffffu, val, o);
        if (lane == 0) atomicAdd(out, val);
    }
}

extern "C" void kernel_launch(void* const* d_in, const int* in_sizes, int n_in,
                              void* d_out, int out_size) {
    (void)in_sizes; (void)n_in; (void)out_size;
    const float* f1    = (const float*)d_in[0];
    const float* f2    = (const float*)d_in[1];
    const int*   label = (const int*)d_in[2];
    float*       out   = (float*)d_out;

    cudaFuncSetAttribute(sim_kernel, cudaFuncAttributeMaxDynamicSharedMemorySize, SMEM_BYTES);

    prep_kernel<<<161, 256>>>(f1, f2, label, out);
    dim3 grid(TWO_N / BM, CS);
    sim_kernel<<<grid, 256, SMEM_BYTES>>>(label);
    finalize_kernel<<<64, 128>>>(label, out);
}

// round 6
// speedup vs baseline: 6.7737x; 1.1985x over previous
#include <cuda_runtime.h>
#include <cstdint>

#define NROWS 4096
#define TWO_N 8192
#define DDIM  64
#define BM 128
#define NTILES 64              // 8192 / 128
#define NPAIRS 2080            // 64*65/2 upper-triangular tile pairs
#define INV_T 20.0f
#define PRESCALE 5.3715827f    // sqrt(20 * log2(e)); dot of scaled = ex2 exponent

// sim smem layout
#define OFF_A    0             // 128x64 bf16 swizzled (16KB)
#define OFF_B    16384         // 16KB
#define OFF_LABR 32768         // 128 ints
#define OFF_LABC 33280         // 128 ints
#define SMEM_BYTES 33792

__device__ __align__(128) uint2 g_feat[TWO_N * 16];   // prescaled bf16, 128B rows
__device__ float g_pt[TWO_N];
__device__ float g_ps[TWO_N];
__device__ float g_pos[NROWS];
__device__ int   g_cnt[64];

static __device__ __forceinline__ uint32_t smem_u32(const void* p) {
    uint32_t a;
    asm("{ .reg .u64 t; cvta.to.shared.u64 t, %1; cvt.u32.u64 %0, t; }" : "=r"(a) : "l"(p));
    return a;
}
static __device__ __forceinline__ float ex2f(float x) {
    float r; asm("ex2.approx.f32 %0, %1;" : "=f"(r) : "f"(x)); return r;
}
static __device__ __forceinline__ uint32_t bf16pack(float lo, float hi) {
    uint32_t r; asm("cvt.rn.bf16x2.f32 %0, %1, %2;" : "=r"(r) : "f"(hi), "f"(lo)); return r;
}
static __device__ __forceinline__ void cpa16(uint32_t dst, const void* src) {
    asm volatile("cp.async.ca.shared.global [%0], [%1], 16;" :: "r"(dst), "l"(src));
}
#define CP_COMMIT() asm volatile("cp.async.commit_group;" ::: "memory")
#define CP_WAIT0()  asm volatile("cp.async.wait_group 0;" ::: "memory")

#define LDSM4(r0, r1, r2, r3, addr) \
    asm volatile("ldmatrix.sync.aligned.m8n8.x4.shared.b16 {%0,%1,%2,%3}, [%4];" \
                 : "=r"(r0), "=r"(r1), "=r"(r2), "=r"(r3) : "r"(addr))

#define MMA16816(d, a, b0, b1) \
    asm volatile("mma.sync.aligned.m16n8k16.row.col.f32.bf16.bf16.f32 " \
                 "{%0,%1,%2,%3}, {%4,%5,%6,%7}, {%8,%9}, {%0,%1,%2,%3};" \
                 : "+f"((d)[0]), "+f"((d)[1]), "+f"((d)[2]), "+f"((d)[3]) \
                 : "r"((a)[0]), "r"((a)[1]), "r"((a)[2]), "r"((a)[3]), "r"(b0), "r"(b1))

// ---- prep: blocks 0..63 convert f1+f2 rows 64b..64b+63, pos dots, zero slices;
//      block 64: hist + out zero ----
__global__ void __launch_bounds__(256)
prep_kernel(const float* __restrict__ f1, const float* __restrict__ f2,
            const int* __restrict__ label, float* __restrict__ out) {
    const int tid = threadIdx.x;
    const int b = blockIdx.x;
    if (b < 64) {
#pragma unroll
        for (int p = 0; p < 4; p++) {
            int r = b * 64 + p * 16 + (tid >> 4);
            int q = tid & 15;
            float4 v1 = ((const float4*)(f1 + r * DDIM))[q];
            float4 v2 = ((const float4*)(f2 + r * DDIM))[q];
            g_feat[r * 16 + q] =
                make_uint2(bf16pack(v1.x * PRESCALE, v1.y * PRESCALE),
                           bf16pack(v1.z * PRESCALE, v1.w * PRESCALE));
            g_feat[(r + NROWS) * 16 + q] =
                make_uint2(bf16pack(v2.x * PRESCALE, v2.y * PRESCALE),
                           bf16pack(v2.z * PRESCALE, v2.w * PRESCALE));
            float d = v1.x * v2.x + v1.y * v2.y + v1.z * v2.z + v1.w * v2.w;
            d += __shfl_xor_sync(0xffffffffu, d, 1);
            d += __shfl_xor_sync(0xffffffffu, d, 2);
            d += __shfl_xor_sync(0xffffffffu, d, 4);
            d += __shfl_xor_sync(0xffffffffu, d, 8);
            if ((tid & 15) == 0) g_pos[r] = __expf(d * INV_T);
        }
        if (tid < 128) { g_pt[b * 128 + tid] = 0.f; g_ps[b * 128 + tid] = 0.f; }
    } else {
        __shared__ int h[64];
        if (tid < 64) h[tid] = 0;
        __syncthreads();
        for (int i = tid; i < NROWS; i += 256) atomicAdd(&h[label[i] & 63], 1);
        __syncthreads();
        if (tid < 64) g_cnt[tid] = h[tid];
        if (tid == 0) out[0] = 0.f;
    }
}

// ---- sim: upper-triangular tile pairs; row sums always, col sums when i<j ----
__global__ void __launch_bounds__(256, 2)
sim_kernel(const int* __restrict__ label) {
    extern __shared__ __align__(1024) char smem[];
    const uint32_t sb = smem_u32(smem);
    const int tid  = threadIdx.x;
    const int lane = tid & 31;
    const int wid  = tid >> 5;
    const int warpM = wid >> 1;
    const int warpN = wid & 1;

    // map linear pair index -> (ti, tj), ti <= tj, row-major upper triangle
    const int t = blockIdx.x;
    int ti = (int)(64.5f - sqrtf(64.5f * 64.5f - 2.0f * (float)t));
    while (64 * ti - ti * (ti - 1) / 2 > t) ti--;
    while (64 * (ti + 1) - (ti + 1) * ti / 2 <= t) ti++;
    const int tj = ti + (t - (64 * ti - ti * (ti - 1) / 2));
    const int row0 = ti * BM;
    const int col0 = tj * BM;

    // prologue: A (block ti), B (block tj), label slices
    {
        const char* gb = (const char*)g_feat;
#pragma unroll
        for (int it = 0; it < 4; it++) {
            int s = it * 256 + tid;
            int r = s >> 3, c = s & 7;
            uint32_t sw = (uint32_t)((c * 16) ^ ((r & 7) << 4));
            cpa16(sb + OFF_A + r * 128 + sw, gb + (size_t)(row0 + r) * 128 + c * 16);
            cpa16(sb + OFF_B + r * 128 + sw, gb + (size_t)(col0 + r) * 128 + c * 16);
        }
        if (tid < 32) cpa16(sb + OFF_LABR + tid * 16, label + (ti & 31) * 128 + tid * 4);
        else if (tid < 64) cpa16(sb + OFF_LABC + (tid - 32) * 16,
                                 label + (tj & 31) * 128 + (tid - 32) * 4);
        CP_COMMIT();
    }

    int rowA[2], nB[4];
#pragma unroll
    for (int mb = 0; mb < 2; mb++)
        rowA[mb] = warpM * 32 + mb * 16 + (lane & 7) + ((lane >> 3) & 1) * 8;
#pragma unroll
    for (int pr = 0; pr < 4; pr++)
        nB[pr] = warpN * 64 + pr * 16 + (lane & 7) + ((lane >> 4) & 1) * 8;
    const int kaA = (lane >> 4) * 16;
    const int kbB = ((lane >> 3) & 1) * 16;

    CP_WAIT0();
    __syncthreads();

    const int* labr = (const int*)(smem + OFF_LABR);
    const int* labc = (const int*)(smem + OFF_LABC);
    int labR[4];
#pragma unroll
    for (int mb = 0; mb < 2; mb++)
#pragma unroll
        for (int h = 0; h < 2; h++)
            labR[mb * 2 + h] = labr[warpM * 32 + mb * 16 + (lane >> 2) + h * 8];

    float acc[2][8][4];
#pragma unroll
    for (int mb = 0; mb < 2; mb++)
#pragma unroll
        for (int nb = 0; nb < 8; nb++)
#pragma unroll
            for (int e = 0; e < 4; e++) acc[mb][nb][e] = 0.f;

#pragma unroll
    for (int kc = 0; kc < 4; kc++) {
        uint32_t a[2][4];
#pragma unroll
        for (int mb = 0; mb < 2; mb++) {
            uint32_t addr = sb + OFF_A + rowA[mb] * 128
                          + ((kc * 32 + kaA) ^ ((rowA[mb] & 7) << 4));
            LDSM4(a[mb][0], a[mb][1], a[mb][2], a[mb][3], addr);
        }
#pragma unroll
        for (int pr = 0; pr < 4; pr++) {
            uint32_t b0, b1, b2, b3;
            uint32_t addr = sb + OFF_B + nB[pr] * 128
                          + ((kc * 32 + kbB) ^ ((nB[pr] & 7) << 4));
            LDSM4(b0, b1, b2, b3, addr);
#pragma unroll
            for (int mb = 0; mb < 2; mb++) {
                MMA16816(acc[mb][2 * pr],     a[mb], b0, b1);
                MMA16816(acc[mb][2 * pr + 1], a[mb], b2, b3);
            }
        }
    }

    // epilogue: exp + row sums (always) + col sums via shuffle reduce (i<j)
    const bool offdiag = (ti != tj);
    float tot[4] = {0.f, 0.f, 0.f, 0.f};
    float smv[4] = {0.f, 0.f, 0.f, 0.f};

#pragma unroll
    for (int nb = 0; nb < 8; nb++) {
        int2 lb2 = *(const int2*)(labc + warpN * 64 + nb * 8 + (lane & 3) * 2);
        float ct0 = 0.f, ct1 = 0.f, cs0 = 0.f, cs1 = 0.f;
#pragma unroll
        for (int mb = 0; mb < 2; mb++)
#pragma unroll
            for (int h = 0; h < 2; h++) {
                float e0 = ex2f(acc[mb][nb][2 * h]);
                float e1 = ex2f(acc[mb][nb][2 * h + 1]);
                float m0 = (lb2.x == labR[mb * 2 + h]) ? e0 : 0.f;
                float m1 = (lb2.y == labR[mb * 2 + h]) ? e1 : 0.f;
                tot[mb * 2 + h] += e0 + e1;
                smv[mb * 2 + h] += m0 + m1;
                ct0 += e0; ct1 += e1;
                cs0 += m0; cs1 += m1;
            }
        if (offdiag) {
            // reduce over the 8 lanes sharing lane&3 (bits 2..4)
#pragma unroll
            for (int o = 4; o <= 16; o <<= 1) {
                ct0 += __shfl_xor_sync(0xffffffffu, ct0, o);
                ct1 += __shfl_xor_sync(0xffffffffu, ct1, o);
                cs0 += __shfl_xor_sync(0xffffffffu, cs0, o);
                cs1 += __shfl_xor_sync(0xffffffffu, cs1, o);
            }
            if ((lane >> 2) == 0) {   // lanes 0..3 hold distinct lane&3 keys
                int gc = col0 + warpN * 64 + nb * 8 + (lane & 3) * 2;
                atomicAdd(&g_pt[gc],     ct0);
                atomicAdd(&g_pt[gc + 1], ct1);
                atomicAdd(&g_ps[gc],     cs0);
                atomicAdd(&g_ps[gc + 1], cs1);
            }
        }
    }

    // row path: quad reduce + atomic add
#pragma unroll
    for (int i = 0; i < 4; i++) {
        float tv = tot[i], sv = smv[i];
        tv += __shfl_xor_sync(0xffffffffu, tv, 1);
        tv += __shfl_xor_sync(0xffffffffu, tv, 2);
        sv += __shfl_xor_sync(0xffffffffu, sv, 1);
        sv += __shfl_xor_sync(0xffffffffu, sv, 2);
        if ((lane & 3) == 0) {
            int grow = row0 + warpM * 32 + (i >> 1) * 16 + (lane >> 2) + (i & 1) * 8;
            atomicAdd(&g_pt[grow], tv);
            atomicAdd(&g_ps[grow], sv);
        }
    }
}

__global__ void __launch_bounds__(128)
finalize_kernel(const int* __restrict__ label, float* __restrict__ out) {
    int i = blockIdx.x * blockDim.x + threadIdx.x;   // 64 x 128 = 8192
    int i0 = i & (NROWS - 1);
    float pos  = g_pos[i0];
    float Ng   = g_pt[i] - g_ps[i];
    float term = log1pf(Ng / pos);            // == -log(pos/(Ng+pos))
    int   gs   = 2 * g_cnt[label[i0] & 63];
    float val  = term / (float)gs;
#pragma unroll
    for (int o = 16; o > 0; o >>= 1) val += __shfl_down_sync(0xffffffffu, val, o);
    __shared__ float ws[4];
    int lane = threadIdx.x & 31, w = threadIdx.x >> 5;
    if (lane == 0) ws[w] = val;
    __syncthreads();
    if (w == 0) {
        val = (lane < 4) ? ws[lane] : 0.f;
#pragma unroll
        for (int o = 2; o > 0; o >>= 1) val += __shfl_down_sync(0xffffffffu, val, o);
        if (lane == 0) atomicAdd(out, val);
    }
}

extern "C" void kernel_launch(void* const* d_in, const int* in_sizes, int n_in,
                              void* d_out, int out_size) {
    (void)in_sizes; (void)n_in; (void)out_size;
    const float* f1    = (const float*)d_in[0];
    const float* f2    = (const float*)d_in[1];
    const int*   label = (const int*)d_in[2];
    float*       out   = (float*)d_out;

    cudaFuncSetAttribute(sim_kernel, cudaFuncAttributeMaxDynamicSharedMemorySize, SMEM_BYTES);

    prep_kernel<<<65, 256>>>(f1, f2, label, out);
    sim_kernel<<<NPAIRS, 256, SMEM_BYTES>>>(label);
    finalize_kernel<<<64, 128>>>(label, out);
}